// round 1
// baseline (speedup 1.0000x reference)
#include <cuda_runtime.h>
#include <cuda_bf16.h>

// Problem constants
#define BSZ 2
#define SEQ 2048
#define HID 2048
#define HD  256
#define NH  8
#define SCALING 0.0625f   // 256^-0.5
#define NEG_INF (-1000000000.0f)

// ---------------- scratch (device globals; no allocs allowed) ----------------
__device__ float g_Qproj[(long)BSZ*SEQ*NH*HD];  // (b,s,h,d) = 8.4M
__device__ float g_Qt   [(long)BSZ*NH*SEQ*HD];  // (b,h,s,d) = 8.4M
__device__ float g_K    [(long)BSZ*SEQ*HD];     // (b,s,d)   = 1.05M
__device__ float g_V    [(long)BSZ*SEQ*HD];
__device__ float g_AO   [(long)BSZ*SEQ*NH*HD];  // (b,s,h*d) = 8.4M

// ---------------- generic tiled SGEMM ----------------
// C = alpha * A @ op(B) (+ causal mask), batched over gridDim.z
// A: M x K row-major (lda), B: K x N (NN, ldb) or N x K (NT, ldb), C: M x N (ldc)
// offsets: A += z*sAz ; B += b*sBb ; C += b*sCb + h*sCh  with b=z/nh, h=z%nh
#define BM 128
#define BN 128
#define BK 8
#define TM 8
#define TN 8

__global__ __launch_bounds__(256, 2)
void sgemm_kernel(const float* __restrict__ A, const float* __restrict__ B,
                  float* __restrict__ C,
                  int M, int N, int K, int lda, int ldb, int ldc,
                  long sAz, long sBb, long sCb, long sCh, int nh,
                  float alpha, int causal, int transB)
{
    const int z = blockIdx.z;
    const int b = z / nh;
    const int h = z % nh;
    A += (long)z * sAz;
    B += (long)b * sBb;
    C += (long)b * sCb + (long)h * sCh;

    __shared__ float As[BK][BM];
    __shared__ float Bs[BK][BN];

    const int tid = threadIdx.x;
    const int cRow = blockIdx.y;
    const int cCol = blockIdx.x;
    const int threadRow = tid / 16;
    const int threadCol = tid % 16;

    // A tile loader: 128 rows x 8 k, one float4 per thread
    const int aRow = tid / 2;
    const int aCol = (tid % 2) * 4;

    float acc[TM][TN];
    #pragma unroll
    for (int m = 0; m < TM; m++)
        #pragma unroll
        for (int n = 0; n < TN; n++) acc[m][n] = 0.0f;

    const float* Aptr = A + (long)(cRow * BM) * lda;
    const float* Bptr = transB ? (B + (long)(cCol * BN) * ldb)
                               : (B + cCol * BN);

    for (int k0 = 0; k0 < K; k0 += BK) {
        // load A (coalesced float4 along K), store transposed
        {
            float4 a = *reinterpret_cast<const float4*>(
                Aptr + (long)aRow * lda + k0 + aCol);
            As[aCol + 0][aRow] = a.x;
            As[aCol + 1][aRow] = a.y;
            As[aCol + 2][aRow] = a.z;
            As[aCol + 3][aRow] = a.w;
        }
        if (!transB) {
            const int r = tid / 32;        // k row 0..7
            const int c = (tid % 32) * 4;  // n col
            float4 bv = *reinterpret_cast<const float4*>(
                Bptr + (long)(k0 + r) * ldb + c);
            *reinterpret_cast<float4*>(&Bs[r][c]) = bv;
        } else {
            const int n  = tid / 2;         // n row 0..127
            const int kk = (tid % 2) * 4;   // k group
            float4 bv = *reinterpret_cast<const float4*>(
                Bptr + (long)n * ldb + k0 + kk);
            Bs[kk + 0][n] = bv.x;
            Bs[kk + 1][n] = bv.y;
            Bs[kk + 2][n] = bv.z;
            Bs[kk + 3][n] = bv.w;
        }
        __syncthreads();

        #pragma unroll
        for (int k = 0; k < BK; k++) {
            float regM[TM], regN[TN];
            #pragma unroll
            for (int m = 0; m < TM; m++) regM[m] = As[k][threadRow * TM + m];
            #pragma unroll
            for (int n = 0; n < TN; n++) regN[n] = Bs[k][threadCol * TN + n];
            #pragma unroll
            for (int m = 0; m < TM; m++)
                #pragma unroll
                for (int n = 0; n < TN; n++)
                    acc[m][n] = fmaf(regM[m], regN[n], acc[m][n]);
        }
        __syncthreads();
    }

    #pragma unroll
    for (int m = 0; m < TM; m++) {
        const int row = cRow * BM + threadRow * TM + m;
        #pragma unroll
        for (int n = 0; n < TN; n++) {
            const int col = cCol * BN + threadCol * TN + n;
            float v = acc[m][n] * alpha;
            if (causal && col > row) v += NEG_INF;
            C[(long)row * ldc + col] = v;
        }
    }
}

// ---------------- RoPE on Q, fused with (b,s,h,d) -> (b,h,s,d) transpose ----
__global__ void rope_q_transpose(const float* __restrict__ Qp,
                                 const float* __restrict__ cosb,
                                 const float* __restrict__ sinb,
                                 float* __restrict__ Qt)
{
    long idx = (long)blockIdx.x * blockDim.x + threadIdx.x; // B*S*NH*(HD/2)
    const int dh = idx & 127;          // 0..127
    long t = idx >> 7;
    const int h = t & 7;  t >>= 3;
    const int s = t & 2047;
    const int b = (int)(t >> 11);

    const float* src = Qp + ((long)(b * SEQ + s) * (NH * HD) + h * HD);
    const float x1 = src[dh];
    const float x2 = src[dh + 128];
    const long cs = (long)(b * SEQ + s) * HD;
    const float c1 = cosb[cs + dh],       s1 = sinb[cs + dh];
    const float c2 = cosb[cs + dh + 128], s2 = sinb[cs + dh + 128];

    float* dst = Qt + (((long)(b * NH + h) * SEQ + s) * HD);
    dst[dh]       = x1 * c1 - x2 * s1;
    dst[dh + 128] = x2 * c2 + x1 * s2;
}

// ---------------- RoPE on K, in place (pairwise) ----------------
__global__ void rope_k_inplace(float* __restrict__ Kp,
                               const float* __restrict__ cosb,
                               const float* __restrict__ sinb)
{
    long idx = (long)blockIdx.x * blockDim.x + threadIdx.x; // B*S*(HD/2)
    const int dh = idx & 127;
    long t = idx >> 7;
    const int s = t & 2047;
    const int b = (int)(t >> 11);

    float* p = Kp + (long)(b * SEQ + s) * HD;
    const float x1 = p[dh];
    const float x2 = p[dh + 128];
    const long cs = (long)(b * SEQ + s) * HD;
    const float c1 = cosb[cs + dh],       s1 = sinb[cs + dh];
    const float c2 = cosb[cs + dh + 128], s2 = sinb[cs + dh + 128];
    p[dh]       = x1 * c1 - x2 * s1;
    p[dh + 128] = x2 * c2 + x1 * s2;
}

// ---------------- row softmax over length-2048 rows, in place --------------
__global__ __launch_bounds__(256)
void softmax_rows(float* __restrict__ W)
{
    const long row = blockIdx.x;
    float* p = W + row * (long)SEQ;
    const int tid = threadIdx.x;
    __shared__ float red[256];

    float v[8];
    #pragma unroll
    for (int j = 0; j < 8; j++) v[j] = p[tid + j * 256];

    float m = v[0];
    #pragma unroll
    for (int j = 1; j < 8; j++) m = fmaxf(m, v[j]);
    red[tid] = m;
    __syncthreads();
    for (int s = 128; s > 0; s >>= 1) {
        if (tid < s) red[tid] = fmaxf(red[tid], red[tid + s]);
        __syncthreads();
    }
    m = red[0];
    __syncthreads();

    float sum = 0.0f;
    #pragma unroll
    for (int j = 0; j < 8; j++) {
        v[j] = __expf(v[j] - m);
        sum += v[j];
    }
    red[tid] = sum;
    __syncthreads();
    for (int s = 128; s > 0; s >>= 1) {
        if (tid < s) red[tid] += red[tid + s];
        __syncthreads();
    }
    const float inv = 1.0f / red[0];
    __syncthreads();

    #pragma unroll
    for (int j = 0; j < 8; j++) p[tid + j * 256] = v[j] * inv;
}

// ---------------- launch ----------------
extern "C" void kernel_launch(void* const* d_in, const int* in_sizes, int n_in,
                              void* d_out, int out_size)
{
    const float* hs   = (const float*)d_in[0]; // (B,S,H)
    const float* cosb = (const float*)d_in[1]; // (B,S,D)
    const float* sinb = (const float*)d_in[2]; // (B,S,D)
    // d_in[3] = attention_mask (causal, reconstructed analytically)
    const float* Wq   = (const float*)d_in[4]; // (H, NH*D)
    const float* Wk   = (const float*)d_in[5]; // (H, D)
    const float* Wv   = (const float*)d_in[6]; // (H, D)
    const float* Wo   = (const float*)d_in[7]; // (NH*D, H)

    float* out_attn = (float*)d_out;                           // (B,S,H)
    float* out_w    = (float*)d_out + (long)BSZ * SEQ * HID;   // (B,NH,S,S)

    float* Qp = g_Qproj;
    float* Qt = g_Qt;
    float* Kb = g_K;
    float* Vb = g_V;
    float* AO = g_AO;
    // get device-symbol addresses via runtime (symbols in same module: direct use ok)

    const int M_tok = BSZ * SEQ;           // 4096
    const long SD   = (long)SEQ * HD;      // 524288
    const long SS   = (long)SEQ * SEQ;     // 4194304

    // 1) Q = hs @ Wq   (4096 x 2048) @ (2048 x 2048)
    sgemm_kernel<<<dim3(HID / BN, M_tok / BM, 1), 256>>>(
        hs, Wq, Qp, M_tok, HID, HID, HID, HID, HID,
        0, 0, 0, 0, 1, 1.0f, 0, 0);

    // 2) K = hs @ Wk   (4096 x 256)
    sgemm_kernel<<<dim3(HD / BN, M_tok / BM, 1), 256>>>(
        hs, Wk, Kb, M_tok, HD, HID, HID, HD, HD,
        0, 0, 0, 0, 1, 1.0f, 0, 0);

    // 3) V = hs @ Wv
    sgemm_kernel<<<dim3(HD / BN, M_tok / BM, 1), 256>>>(
        hs, Wv, Vb, M_tok, HD, HID, HID, HD, HD,
        0, 0, 0, 0, 1, 1.0f, 0, 0);

    // 4) RoPE Q + transpose to (b,h,s,d)
    {
        long n = (long)BSZ * SEQ * NH * (HD / 2);
        rope_q_transpose<<<(unsigned)(n / 256), 256>>>(Qp, cosb, sinb, Qt);
    }
    // 5) RoPE K in place
    {
        long n = (long)BSZ * SEQ * (HD / 2);
        rope_k_inplace<<<(unsigned)(n / 256), 256>>>(Kb, cosb, sinb);
    }

    // 6) scores = scale * Q @ K^T + causal  -> out_w (logits), per (b,h)
    sgemm_kernel<<<dim3(SEQ / BN, SEQ / BM, BSZ * NH), 256>>>(
        Qt, Kb, out_w, SEQ, SEQ, HD, HD, HD, SEQ,
        SD /*A per z*/, SD /*B per b*/,
        (long)NH * SS /*C per b*/, SS /*C per h*/, NH,
        SCALING, 1, 1);

    // 7) softmax rows, in place in out_w
    softmax_rows<<<(unsigned)((long)BSZ * NH * SEQ), 256>>>(out_w);

    // 8) attn_out(b,s,h,d) = P @ V    per (b,h): (2048x2048)@(2048x256)
    sgemm_kernel<<<dim3(HD / BN, SEQ / BM, BSZ * NH), 256>>>(
        out_w, Vb, AO, SEQ, HD, SEQ, SEQ, HD, NH * HD,
        SS /*A per z*/, SD /*B per b*/,
        (long)SEQ * NH * HD /*C per b*/, (long)HD /*C per h*/, NH,
        1.0f, 0, 0);

    // 9) out = AO @ Wo   (4096 x 2048) @ (2048 x 2048)
    sgemm_kernel<<<dim3(HID / BN, M_tok / BM, 1), 256>>>(
        AO, Wo, out_attn, M_tok, HID, NH * HD, NH * HD, HID, HID,
        0, 0, 0, 0, 1, 1.0f, 0, 0);
}